// round 8
// baseline (speedup 1.0000x reference)
#include <cuda_runtime.h>
#include <cstdint>

// ---------------------------------------------------------------------------
// getMetric: DOA localization metrics (ACC + MAE[ele, azi, aziele])
//
// R8: 3 independent bulk-async rings per SM. Grid = 444 CTAs (3/SM) x 256
// threads; each CTA streams 256-item tiles through its own 3-stage x 24KB
// smem ring (72KB/CTA, 216KB/SM). R7's single-ring-per-SM exposed the
// per-tile handshake (full-wait -> compute -> empty-arrive -> refill)
// serially: memory idled ~40% of cycles. With 3 rings/SM those exposed
// windows overlap with the other CTAs' bulk traffic.
// ---------------------------------------------------------------------------

#define DEG2RAD 0.017453292519943295f
#define RAD2DEG 57.295779513082323f
#define VAD_TH  (2.0f / 3.0f)
#define AE_TH   30.0f
#define CLIPV   0.99999f

#define NUM_CTAS   444           // 148 SMs * 3
#define THREADS    256
#define TILE       256           // items per tile = THREADS (1 item/thread)
#define NSTAGES    3

// per-stage smem layout (bytes)
#define OFF_DGT     0            // doa_gt  : TILE*32 = 8192
#define OFF_DES     8192         // doa_est : 8192
#define OFF_VGT     16384        // vad_gt  : TILE*16 = 4096
#define OFF_VES     20480        // vad_est : 4096
#define STAGE_BYTES 24576
#define BAR_OFF     (NSTAGES * STAGE_BYTES)          // 73728
#define SMEM_TOTAL  (BAR_OFF + 2 * NSTAGES * 8)

__device__ float        g_sums[5];   // act, corr, ele, azi, aziele (zero-init)
__device__ unsigned int g_done;      // ticket counter (zero-init)

// ---- PTX helpers -----------------------------------------------------------
__device__ __forceinline__ uint32_t smem_u32(const void* p) {
    uint32_t a;
    asm("{ .reg .u64 t; cvta.to.shared.u64 t, %1; cvt.u32.u64 %0, t; }"
        : "=r"(a) : "l"(p));
    return a;
}

#define MBAR_INIT(addr, cnt) \
    asm volatile("mbarrier.init.shared.b64 [%0], %1;" \
                 :: "r"(addr), "r"((uint32_t)(cnt)) : "memory")

#define MBAR_INVAL(addr) \
    asm volatile("mbarrier.inval.shared.b64 [%0];" :: "r"(addr) : "memory")

#define MBAR_EXPECT_TX(addr, tx) \
    asm volatile("mbarrier.arrive.expect_tx.shared.b64 _, [%0], %1;" \
                 :: "r"(addr), "r"((uint32_t)(tx)) : "memory")

#define MBAR_ARRIVE(addr) \
    asm volatile("mbarrier.arrive.shared.b64 _, [%0];" :: "r"(addr) : "memory")

#define MBAR_WAIT_PARITY(mbar, parity) do {                                   \
    uint32_t _m = (mbar); uint32_t _p = (parity); uint32_t _ok;               \
    asm volatile("{\n\t.reg .pred p;\n\t"                                     \
        "mbarrier.try_wait.parity.acquire.cta.shared::cta.b64 p, [%1], %2;\n\t"\
        "selp.b32 %0, 1, 0, p;\n\t}"                                          \
        : "=r"(_ok) : "r"(_m), "r"(_p) : "memory");                           \
    if (!_ok) {                                                               \
        asm volatile("{\n\t.reg .pred P1;\n\t"                                \
            "WL_%=:\n\t"                                                      \
            "mbarrier.try_wait.parity.acquire.cta.shared::cta.b64 P1, [%0], %1, 0x989680;\n\t" \
            "@P1 bra.uni WD_%=;\n\t"                                          \
            "bra.uni WL_%=;\n\t"                                              \
            "WD_%=:\n\t}" :: "r"(_m), "r"(_p) : "memory");                    \
    }                                                                         \
} while (0)

#define BULK_G2S(dst_smem, src_gmem, nbytes, mbar) \
    asm volatile("cp.async.bulk.shared::cta.global.mbarrier::complete_tx::bytes " \
                 "[%0], [%1], %2, [%3];" \
                 :: "r"(dst_smem), "l"(src_gmem), "r"((uint32_t)(nbytes)), \
                    "r"(mbar) : "memory")

// ---- math ------------------------------------------------------------------
// Abramowitz & Stegun 4.4.47 polynomial acos, |err| <= ~2e-8 rad.
__device__ __forceinline__ float fast_acos(float x) {
    float ax = fabsf(x);
    float p = -0.0012624911f;
    p = fmaf(p, ax,  0.0066700901f);
    p = fmaf(p, ax, -0.0170881256f);
    p = fmaf(p, ax,  0.0308918810f);
    p = fmaf(p, ax, -0.0501743046f);
    p = fmaf(p, ax,  0.0889789874f);
    p = fmaf(p, ax, -0.2145988016f);
    p = fmaf(p, ax,  1.5707963050f);
    float r = p * sqrtf(1.0f - ax);
    return (x < 0.0f) ? (3.14159265358979f - r) : r;
}

__device__ __forceinline__ void proc_one(
    float elg, float azg, float ele_, float aze, float vg, float ve,
    float& s_act, float& s_corr, float& s_ele, float& s_azi, float& s_ae)
{
    float vgf = (vg > VAD_TH) ? 1.0f : 0.0f;
    float vef = (ve > VAD_TH) ? vgf : 0.0f;

    // azimuth error: |mod(est - gt + 180, 360) - 180|
    float d = aze - azg;                        // (-360, 360)
    float r = d + 180.0f;                       // (-180, 540)
    r -= 360.0f * floorf(r * (1.0f / 360.0f));  // [0, 360)
    float azi_err = fabsf(r - 180.0f);

    float dele = ele_ - elg;
    float ele_err = fabsf(dele);

    // great-circle error via product-to-sum identity
    float cde = __cosf(dele * DEG2RAD);
    float cse = __cosf((ele_ + elg) * DEG2RAD);
    float cda = __cosf(d * DEG2RAD);
    float aux = 0.5f * fmaf(cde, 1.0f + cda, cse * (1.0f - cda));
    aux = fminf(fmaxf(aux, -CLIPV), CLIPV);
    float ae_deg = fast_acos(aux) * RAD2DEG;

    s_act  += vgf;
    s_corr += (azi_err < AE_TH) ? vef : 0.0f;
    s_ele   = fmaf(vgf, ele_err,  s_ele);
    s_azi   = fmaf(vgf, azi_err,  s_azi);
    s_ae    = fmaf(vgf, ae_deg,   s_ae);
}

// ---- kernel -----------------------------------------------------------------
__global__ void __launch_bounds__(THREADS, 3)
getMetric_kernel(const char* __restrict__ doa_gt,
                 const char* __restrict__ vad_gt,
                 const char* __restrict__ doa_est,
                 const char* __restrict__ vad_est,
                 float* __restrict__ out,
                 int n_items)
{
    extern __shared__ char smem[];
    const uint32_t sb     = smem_u32(smem);
    const uint32_t fullb  = sb + BAR_OFF;               // full[s]  at +8*s
    const uint32_t emptyb = sb + BAR_OFF + NSTAGES * 8; // empty[s] at +8*s
    const int tid = threadIdx.x;

    if (tid == 0) {
        #pragma unroll
        for (int s = 0; s < NSTAGES; s++) {
            MBAR_INIT(fullb  + 8 * s, 1);
            MBAR_INIT(emptyb + 8 * s, THREADS);
        }
    }
    __syncthreads();

    // tile range for this CTA (contiguous)
    const int ntiles = (n_items + TILE - 1) / TILE;
    const int per    = (ntiles + gridDim.x - 1) / gridDim.x;
    const int t0     = min((int)blockIdx.x * per, ntiles);
    const int t1     = min(t0 + per, ntiles);
    const int my_n   = t1 - t0;

    float s_act = 0.f, s_corr = 0.f, s_ele = 0.f, s_azi = 0.f, s_ae = 0.f;

    // ---- prologue: fill up to NSTAGES stages (fresh barriers -> no wait) ----
    int prod_l = 0;
    if (tid == 0) {
        const int pre = my_n < NSTAGES ? my_n : NSTAGES;
        for (; prod_l < pre; prod_l++) {
            const long base = (long)(t0 + prod_l) * TILE;
            const int  cnt  = min(TILE, n_items - (int)base);
            const uint32_t st = sb + prod_l * STAGE_BYTES;
            const uint32_t fb = fullb + 8 * prod_l;
            MBAR_EXPECT_TX(fb, cnt * 96);
            BULK_G2S(st + OFF_DGT, doa_gt  + base * 32, cnt * 32, fb);
            BULK_G2S(st + OFF_DES, doa_est + base * 32, cnt * 32, fb);
            BULK_G2S(st + OFF_VGT, vad_gt  + base * 16, cnt * 16, fb);
            BULK_G2S(st + OFF_VES, vad_est + base * 16, cnt * 16, fb);
        }
    }

    // ---- main loop: cursor-tracked stage/phase (NSTAGES=3, no pow2) ----
    int cs = 0, cph = 0;     // consumer stage/phase
    int ps = 0, pph = 0;     // producer (refill) stage/phase

    for (int l = 0; l < my_n; l++) {
        MBAR_WAIT_PARITY(fullb + 8 * cs, cph);

        const char* st = smem + (size_t)cs * STAGE_BYTES;
        const long  gitem = (long)(t0 + l) * TILE + tid;
        if (gitem < n_items) {
            const float4* dg  = (const float4*)(st + OFF_DGT);
            const float4* de  = (const float4*)(st + OFF_DES);
            const float4* vgp = (const float4*)(st + OFF_VGT);
            const float4* vep = (const float4*)(st + OFF_VES);
            float4 eg = dg[2 * tid];
            float4 ag = dg[2 * tid + 1];
            float4 ee = de[2 * tid];
            float4 ae = de[2 * tid + 1];
            float4 vg = vgp[tid];
            float4 ve = vep[tid];
            proc_one(eg.x, ag.x, ee.x, ae.x, vg.x, ve.x, s_act, s_corr, s_ele, s_azi, s_ae);
            proc_one(eg.y, ag.y, ee.y, ae.y, vg.y, ve.y, s_act, s_corr, s_ele, s_azi, s_ae);
            proc_one(eg.z, ag.z, ee.z, ae.z, vg.z, ve.z, s_act, s_corr, s_ele, s_azi, s_ae);
            proc_one(eg.w, ag.w, ee.w, ae.w, vg.w, ve.w, s_act, s_corr, s_ele, s_azi, s_ae);
        }
        MBAR_ARRIVE(emptyb + 8 * cs);
        if (++cs == NSTAGES) { cs = 0; cph ^= 1; }

        // producer: refill the just-freed stage for tile prod_l
        if (tid == 0 && prod_l < my_n) {
            MBAR_WAIT_PARITY(emptyb + 8 * ps, pph);
            const long base = (long)(t0 + prod_l) * TILE;
            const int  cnt  = min(TILE, n_items - (int)base);
            const uint32_t st2 = sb + ps * STAGE_BYTES;
            const uint32_t fb  = fullb + 8 * ps;
            MBAR_EXPECT_TX(fb, cnt * 96);
            BULK_G2S(st2 + OFF_DGT, doa_gt  + base * 32, cnt * 32, fb);
            BULK_G2S(st2 + OFF_DES, doa_est + base * 32, cnt * 32, fb);
            BULK_G2S(st2 + OFF_VGT, vad_gt  + base * 16, cnt * 16, fb);
            BULK_G2S(st2 + OFF_VES, vad_est + base * 16, cnt * 16, fb);
            prod_l++;
            if (++ps == NSTAGES) { ps = 0; pph ^= 1; }
        }
    }

    __syncthreads();
    if (tid == 0) {
        #pragma unroll
        for (int s = 0; s < NSTAGES; s++) {
            MBAR_INVAL(fullb  + 8 * s);
            MBAR_INVAL(emptyb + 8 * s);
        }
    }

    // ---- warp reduction ----
    #pragma unroll
    for (int o = 16; o > 0; o >>= 1) {
        s_act  += __shfl_xor_sync(0xFFFFFFFFu, s_act,  o);
        s_corr += __shfl_xor_sync(0xFFFFFFFFu, s_corr, o);
        s_ele  += __shfl_xor_sync(0xFFFFFFFFu, s_ele,  o);
        s_azi  += __shfl_xor_sync(0xFFFFFFFFu, s_azi,  o);
        s_ae   += __shfl_xor_sync(0xFFFFFFFFu, s_ae,   o);
    }

    // ---- block reduction (8 warps @ 256 threads) ----
    __shared__ float rsm[5][8];
    const int lane = tid & 31;
    const int wid  = tid >> 5;
    if (lane == 0) {
        rsm[0][wid] = s_act; rsm[1][wid] = s_corr; rsm[2][wid] = s_ele;
        rsm[3][wid] = s_azi; rsm[4][wid] = s_ae;
    }
    __syncthreads();

    if (tid == 0) {
        float b[5];
        #pragma unroll
        for (int k = 0; k < 5; k++) {
            float v = rsm[k][0];
            #pragma unroll
            for (int w = 1; w < 8; w++) v += rsm[k][w];
            b[k] = v;
        }
        #pragma unroll
        for (int k = 0; k < 5; k++) atomicAdd(&g_sums[k], b[k]);

        __threadfence();
        unsigned int ticket = atomicAdd(&g_done, 1u);
        if (ticket == gridDim.x - 1) {
            float act   = atomicAdd(&g_sums[0], 0.0f);
            float corr  = atomicAdd(&g_sums[1], 0.0f);
            float ele   = atomicAdd(&g_sums[2], 0.0f);
            float azi   = atomicAdd(&g_sums[3], 0.0f);
            float aziel = atomicAdd(&g_sums[4], 0.0f);

            float inv = 1.0f / act;
            out[0] = corr  * inv;   // ACC
            out[1] = ele   * inv;   // MAE ele
            out[2] = azi   * inv;   // MAE azi
            out[3] = aziel * inv;   // MAE aziele

            // self-reset for next graph replay
            #pragma unroll
            for (int k = 0; k < 5; k++) atomicExch(&g_sums[k], 0.0f);
            atomicExch(&g_done, 0u);
        }
    }
}

extern "C" void kernel_launch(void* const* d_in, const int* in_sizes, int n_in,
                              void* d_out, int out_size)
{
    const char* doa_gt  = (const char*)d_in[0];
    const char* vad_gt  = (const char*)d_in[1];
    const char* doa_est = (const char*)d_in[2];
    const char* vad_est = (const char*)d_in[3];
    float* out = (float*)d_out;

    const int n_items = in_sizes[1] / 4;   // nb*nt  (vad has ns=4 per item)

    cudaFuncSetAttribute(getMetric_kernel,
                         cudaFuncAttributeMaxDynamicSharedMemorySize, SMEM_TOTAL);

    getMetric_kernel<<<NUM_CTAS, THREADS, SMEM_TOTAL>>>(
        doa_gt, vad_gt, doa_est, vad_est, out, n_items);
}

// round 9
// speedup vs baseline: 1.2600x; 1.2600x over previous
#include <cuda_runtime.h>

// ---------------------------------------------------------------------------
// getMetric: DOA localization metrics (ACC + MAE[ele, azi, aziele])
//
// R9: R4 base (best: 16.9us, depth-2 pipelined grid-stride, 592 CTAs x 256,
// one resident wave) + instruction diet:
//  - azimuth wrap via fabs-chain (exact for |d|<360): 2 FADD + free FABS
//    instead of floorf+mul+fma+sub
//  - 4-term A&S acos poly (err 0.0038 deg << 1e-3 rel gate): -4 FMA/source
//  - sqrt.approx.f32 (single MUFU op) in acos
// ~20% fewer instructions in the compute phase of each pipeline round.
// ---------------------------------------------------------------------------

#define DEG2RAD 0.017453292519943295f
#define RAD2DEG 57.295779513082323f
#define VAD_TH  (2.0f / 3.0f)
#define AE_TH   30.0f
#define CLIPV   0.99999f

#define NUM_SMS 148
#define CTAS_PER_SM 4

__device__ float        g_sums[5];   // act, corr, ele, azi, aziele (zero-init at load)
__device__ unsigned int g_done;      // ticket counter (zero-init at load)

// Abramowitz & Stegun 4.4.45 polynomial acos, |err| <= 6.7e-5 rad (0.0038 deg).
__device__ __forceinline__ float fast_acos(float x) {
    float ax = fabsf(x);
    float p = fmaf(fmaf(fmaf(-0.0187293f, ax, 0.0742610f), ax, -0.2121144f),
                   ax, 1.5707288f);
    float s;
    asm("sqrt.approx.f32 %0, %1;" : "=f"(s) : "f"(1.0f - ax));
    float r = p * s;
    return (x < 0.0f) ? (3.14159265358979f - r) : r;
}

struct Item { float4 eg, ag, ee, ae, vg, ve; };

__device__ __forceinline__ Item load_item(
    const float4* __restrict__ doa_gt, const float4* __restrict__ vad_gt,
    const float4* __restrict__ doa_est, const float4* __restrict__ vad_est,
    int i)
{
    Item it;
    it.eg = doa_gt [2 * i];
    it.ag = doa_gt [2 * i + 1];
    it.ee = doa_est[2 * i];
    it.ae = doa_est[2 * i + 1];
    it.vg = vad_gt [i];
    it.ve = vad_est[i];
    return it;
}

__device__ __forceinline__ void proc_one(
    float elg, float azg, float ele_, float aze, float vg, float ve,
    float& s_act, float& s_corr, float& s_ele, float& s_azi, float& s_ae)
{
    float vgf = (vg > VAD_TH) ? 1.0f : 0.0f;
    float vef = (ve > VAD_TH) ? vgf : 0.0f;

    // azimuth error: |mod(d+180,360)-180| == | ||d|-180| - 180 |  for |d|<360
    // (FABS is a free SASS operand modifier -> 2 FADD total)
    float d = aze - azg;                        // (-360, 360)
    float azi_err = fabsf(fabsf(fabsf(d) - 180.0f) - 180.0f);

    float dele = ele_ - elg;
    float ele_err = fabsf(dele);

    // great-circle error via product-to-sum:
    //   cos(a)cos(b) + sin(a)sin(b)cos(c)
    // = 0.5*[cos(a-b)*(1+cos(c)) + cos(a+b)*(1-cos(c))]
    float cde = __cosf(dele * DEG2RAD);          // cos(ele_gt - ele_es)
    float cse = __cosf((ele_ + elg) * DEG2RAD);  // cos(ele_gt + ele_es)
    float cda = __cosf(d * DEG2RAD);             // cos(azi_gt - azi_es)
    float aux = 0.5f * fmaf(cde, 1.0f + cda, cse * (1.0f - cda));
    aux = fminf(fmaxf(aux, -CLIPV), CLIPV);
    float ae_deg = fast_acos(aux) * RAD2DEG;

    s_act  += vgf;
    s_corr += (azi_err < AE_TH) ? vef : 0.0f;
    s_ele   = fmaf(vgf, ele_err,  s_ele);
    s_azi   = fmaf(vgf, azi_err,  s_azi);
    s_ae    = fmaf(vgf, ae_deg,   s_ae);
}

__device__ __forceinline__ void proc_item(
    const Item& it,
    float& s_act, float& s_corr, float& s_ele, float& s_azi, float& s_ae)
{
    proc_one(it.eg.x, it.ag.x, it.ee.x, it.ae.x, it.vg.x, it.ve.x, s_act, s_corr, s_ele, s_azi, s_ae);
    proc_one(it.eg.y, it.ag.y, it.ee.y, it.ae.y, it.vg.y, it.ve.y, s_act, s_corr, s_ele, s_azi, s_ae);
    proc_one(it.eg.z, it.ag.z, it.ee.z, it.ae.z, it.vg.z, it.ve.z, s_act, s_corr, s_ele, s_azi, s_ae);
    proc_one(it.eg.w, it.ag.w, it.ee.w, it.ae.w, it.vg.w, it.ve.w, s_act, s_corr, s_ele, s_azi, s_ae);
}

__global__ void __launch_bounds__(256, CTAS_PER_SM)
getMetric_kernel(const float4* __restrict__ doa_gt,
                 const float4* __restrict__ vad_gt,
                 const float4* __restrict__ doa_est,
                 const float4* __restrict__ vad_est,
                 float* __restrict__ out,
                 int n_items)
{
    float s_act = 0.f, s_corr = 0.f, s_ele = 0.f, s_azi = 0.f, s_ae = 0.f;

    const int stride = gridDim.x * blockDim.x;
    int i = blockIdx.x * blockDim.x + threadIdx.x;

    if (i < n_items) {
        Item cur = load_item(doa_gt, vad_gt, doa_est, vad_est, i);
        for (;;) {
            const int j = i + stride;
            const bool more = (j < n_items);
            Item nxt;
            if (more)
                nxt = load_item(doa_gt, vad_gt, doa_est, vad_est, j);  // prefetch
            proc_item(cur, s_act, s_corr, s_ele, s_azi, s_ae);
            if (!more) break;
            cur = nxt;
            i = j;
        }
    }

    // ---- warp reduction ----
    #pragma unroll
    for (int o = 16; o > 0; o >>= 1) {
        s_act  += __shfl_xor_sync(0xFFFFFFFFu, s_act,  o);
        s_corr += __shfl_xor_sync(0xFFFFFFFFu, s_corr, o);
        s_ele  += __shfl_xor_sync(0xFFFFFFFFu, s_ele,  o);
        s_azi  += __shfl_xor_sync(0xFFFFFFFFu, s_azi,  o);
        s_ae   += __shfl_xor_sync(0xFFFFFFFFu, s_ae,   o);
    }

    // ---- block reduction (8 warps @ 256 threads) ----
    __shared__ float smem[5][8];
    const int lane = threadIdx.x & 31;
    const int wid  = threadIdx.x >> 5;
    if (lane == 0) {
        smem[0][wid] = s_act; smem[1][wid] = s_corr; smem[2][wid] = s_ele;
        smem[3][wid] = s_azi; smem[4][wid] = s_ae;
    }
    __syncthreads();

    if (threadIdx.x == 0) {
        float b[5];
        #pragma unroll
        for (int k = 0; k < 5; k++) {
            float v = smem[k][0];
            #pragma unroll
            for (int w = 1; w < 8; w++) v += smem[k][w];
            b[k] = v;
        }
        #pragma unroll
        for (int k = 0; k < 5; k++) atomicAdd(&g_sums[k], b[k]);

        __threadfence();
        unsigned int ticket = atomicAdd(&g_done, 1u);
        if (ticket == gridDim.x - 1) {
            float act   = atomicAdd(&g_sums[0], 0.0f);
            float corr  = atomicAdd(&g_sums[1], 0.0f);
            float ele   = atomicAdd(&g_sums[2], 0.0f);
            float azi   = atomicAdd(&g_sums[3], 0.0f);
            float aziel = atomicAdd(&g_sums[4], 0.0f);

            float inv = 1.0f / act;
            out[0] = corr  * inv;   // ACC
            out[1] = ele   * inv;   // MAE ele
            out[2] = azi   * inv;   // MAE azi
            out[3] = aziel * inv;   // MAE aziele

            // self-reset for next graph replay
            #pragma unroll
            for (int k = 0; k < 5; k++) atomicExch(&g_sums[k], 0.0f);
            atomicExch(&g_done, 0u);
        }
    }
}

extern "C" void kernel_launch(void* const* d_in, const int* in_sizes, int n_in,
                              void* d_out, int out_size)
{
    const float4* doa_gt  = (const float4*)d_in[0];
    const float4* vad_gt  = (const float4*)d_in[1];
    const float4* doa_est = (const float4*)d_in[2];
    const float4* vad_est = (const float4*)d_in[3];
    float* out = (float*)d_out;

    const int n_items = in_sizes[1] / 4;   // nb*nt  (vad has ns=4 per item)

    const int threads = 256;
    const int blocks  = NUM_SMS * CTAS_PER_SM;   // exactly one resident wave
    getMetric_kernel<<<blocks, threads>>>(doa_gt, vad_gt, doa_est, vad_est,
                                          out, n_items);
}